// round 4
// baseline (speedup 1.0000x reference)
#include <cuda_runtime.h>
#include <math.h>
#include <stdint.h>

#define NB      8
#define NSEQ    256
#define DIMC    512
#define NHEADS  8
#define DH      64
#define NTOK    (NB * NSEQ)       // 2048
#define QKV3    (3 * DIMC)        // 1536
#define SCALE   0.125f            // 64^-0.5

// ---------------- scratch (no cudaMalloc allowed) ----------------
__device__ float2 g_stats[NTOK];                         // per-row (mu, inv)
__device__ float g_qkv[NTOK * QKV3];                     // 12.6 MB
__device__ float g_attn[NB * NHEADS * NSEQ * NSEQ];      // 16.8 MB  [b][h][n][m]
__device__ float g_o[NTOK * DIMC];                       // 4 MB     [b][n][h*64+d]

// ---------------- tf32 mma helpers ----------------
__device__ __forceinline__ uint32_t f2tf(float x) {
  uint32_t r;
  asm("cvt.rna.tf32.f32 %0, %1;" : "=r"(r) : "f"(x));
  return r;
}

__device__ __forceinline__ void mma_tf32(float c[4],
    uint32_t a0, uint32_t a1, uint32_t a2, uint32_t a3,
    uint32_t b0, uint32_t b1) {
  asm volatile(
    "mma.sync.aligned.m16n8k8.row.col.f32.tf32.tf32.f32 "
    "{%0,%1,%2,%3}, {%4,%5,%6,%7}, {%8,%9}, {%0,%1,%2,%3};\n"
    : "+f"(c[0]), "+f"(c[1]), "+f"(c[2]), "+f"(c[3])
    : "r"(a0), "r"(a1), "r"(a2), "r"(a3), "r"(b0), "r"(b1));
}

// =================================================================
// LN stats: one warp per row -> (mu, rsqrt(var+eps))
// =================================================================
__global__ __launch_bounds__(256) void ln_stats_kernel(const float* __restrict__ x) {
  int row = blockIdx.x * 8 + (threadIdx.x >> 5);
  int l = threadIdx.x & 31;
  const float* xr = x + (size_t)row * DIMC;
  float s = 0.f, sq = 0.f;
  #pragma unroll
  for (int j = 0; j < 4; ++j) {
    float4 v = *(const float4*)&xr[l * 4 + j * 128];
    s += v.x + v.y + v.z + v.w;
    sq += v.x * v.x + v.y * v.y + v.z * v.z + v.w * v.w;
  }
  #pragma unroll
  for (int o = 16; o; o >>= 1) {
    s  += __shfl_xor_sync(0xffffffffu, s, o);
    sq += __shfl_xor_sync(0xffffffffu, sq, o);
  }
  if (l == 0) {
    float mu = s * (1.f / DIMC);
    float var = sq * (1.f / DIMC) - mu * mu;
    g_stats[row] = make_float2(mu, rsqrtf(var + 1e-5f));
  }
}

// =================================================================
// tf32 GEMM: C[M,N] = A[M,K] @ B[K,N] (+bias), optional fused LN on A
// BM=128, BN template, BK=16, 256 threads, double-buffered.
// =================================================================
template<int BN, int WARPS_M, int WARPS_N, bool LNF>
__global__ __launch_bounds__(256) void gemm_tf32(
    const float* __restrict__ A, const float* __restrict__ B,
    const float* __restrict__ bias, float* __restrict__ C,
    const float* __restrict__ gamma, const float* __restrict__ beta,
    int M, int N, int K) {
  constexpr int BM = 128, BK = 16;
  constexpr int WTM = BM / WARPS_M;
  constexpr int WTN = BN / WARPS_N;
  constexpr int MI = WTM / 16;
  constexpr int NI = WTN / 8;
  constexpr int AS = BK + 4;
  constexpr int BS = BN + 4;
  constexpr int BF4 = (BK * BN) / (256 * 4);

  __shared__ uint32_t As[2][BM * AS];
  __shared__ uint32_t Bs[2][BK * BS];

  int t = threadIdx.x;
  int w = t >> 5, l = t & 31;
  int g = l >> 2, tg = l & 3;
  int wm = (w % WARPS_M) * WTM;
  int wn = (w / WARPS_M) * WTN;
  int bm = blockIdx.y * BM, bn = blockIdx.x * BN;

  int arow = t >> 1, akh = (t & 1) * 8;
  const float* Aptr = A + (size_t)(bm + arow) * K + akh;

  float mu = 0.f, inv = 1.f;
  if (LNF) {
    float2 st = g_stats[bm + arow];
    mu = st.x; inv = st.y;
  }

  int brow[BF4], bcol[BF4];
  #pragma unroll
  for (int j = 0; j < BF4; ++j) {
    int lin = (j * 256 + t) * 4;
    brow[j] = lin / BN;
    bcol[j] = lin % BN;
  }

  float c[MI][NI][4];
  #pragma unroll
  for (int i = 0; i < MI; ++i)
    #pragma unroll
    for (int j = 0; j < NI; ++j)
      #pragma unroll
      for (int q = 0; q < 4; ++q) c[i][j][q] = 0.f;

  float4 av0, av1, bv[BF4];
  float4 gv0, gv1, bb0, bb1;

  auto loadA = [&](int k0) {
    av0 = *(const float4*)(Aptr + k0);
    av1 = *(const float4*)(Aptr + k0 + 4);
    if (LNF) {
      gv0 = *(const float4*)&gamma[k0 + akh];
      gv1 = *(const float4*)&gamma[k0 + akh + 4];
      bb0 = *(const float4*)&beta[k0 + akh];
      bb1 = *(const float4*)&beta[k0 + akh + 4];
    }
  };
  auto stageA = [&](int buf) {
    float4 v0 = av0, v1 = av1;
    if (LNF) {
      v0.x = (v0.x - mu) * inv * gv0.x + bb0.x;
      v0.y = (v0.y - mu) * inv * gv0.y + bb0.y;
      v0.z = (v0.z - mu) * inv * gv0.z + bb0.z;
      v0.w = (v0.w - mu) * inv * gv0.w + bb0.w;
      v1.x = (v1.x - mu) * inv * gv1.x + bb1.x;
      v1.y = (v1.y - mu) * inv * gv1.y + bb1.y;
      v1.z = (v1.z - mu) * inv * gv1.z + bb1.z;
      v1.w = (v1.w - mu) * inv * gv1.w + bb1.w;
    }
    uint32_t* as = As[buf] + arow * AS + akh;
    as[0]=f2tf(v0.x); as[1]=f2tf(v0.y); as[2]=f2tf(v0.z); as[3]=f2tf(v0.w);
    as[4]=f2tf(v1.x); as[5]=f2tf(v1.y); as[6]=f2tf(v1.z); as[7]=f2tf(v1.w);
  };

  // prologue
  loadA(0);
  #pragma unroll
  for (int j = 0; j < BF4; ++j)
    bv[j] = *(const float4*)(B + (size_t)brow[j] * N + bn + bcol[j]);
  stageA(0);
  #pragma unroll
  for (int j = 0; j < BF4; ++j) {
    uint32_t* bs = Bs[0] + brow[j] * BS + bcol[j];
    bs[0]=f2tf(bv[j].x); bs[1]=f2tf(bv[j].y); bs[2]=f2tf(bv[j].z); bs[3]=f2tf(bv[j].w);
  }
  __syncthreads();

  int nk = K / BK;
  for (int it = 0; it < nk; ++it) {
    int buf = it & 1;
    bool more = (it + 1 < nk);
    if (more) {
      int k0 = (it + 1) * BK;
      loadA(k0);
      #pragma unroll
      for (int j = 0; j < BF4; ++j)
        bv[j] = *(const float4*)(B + (size_t)(k0 + brow[j]) * N + bn + bcol[j]);
    }

    #pragma unroll
    for (int kk = 0; kk < BK; kk += 8) {
      uint32_t af[MI][4], bf[NI][2];
      #pragma unroll
      for (int i = 0; i < MI; ++i) {
        const uint32_t* p = As[buf] + (wm + i * 16 + g) * AS + kk + tg;
        af[i][0] = p[0];
        af[i][1] = p[8 * AS];
        af[i][2] = p[4];
        af[i][3] = p[8 * AS + 4];
      }
      #pragma unroll
      for (int j = 0; j < NI; ++j) {
        const uint32_t* p = Bs[buf] + (kk + tg) * BS + wn + j * 8 + g;
        bf[j][0] = p[0];
        bf[j][1] = p[4 * BS];
      }
      #pragma unroll
      for (int i = 0; i < MI; ++i)
        #pragma unroll
        for (int j = 0; j < NI; ++j)
          mma_tf32(c[i][j], af[i][0], af[i][1], af[i][2], af[i][3],
                   bf[j][0], bf[j][1]);
    }

    if (more) {
      int nb = buf ^ 1;
      stageA(nb);
      #pragma unroll
      for (int j = 0; j < BF4; ++j) {
        uint32_t* bs = Bs[nb] + brow[j] * BS + bcol[j];
        bs[0]=f2tf(bv[j].x); bs[1]=f2tf(bv[j].y); bs[2]=f2tf(bv[j].z); bs[3]=f2tf(bv[j].w);
      }
    }
    __syncthreads();
  }

  #pragma unroll
  for (int i = 0; i < MI; ++i) {
    int r0 = bm + wm + i * 16 + g;
    #pragma unroll
    for (int j = 0; j < NI; ++j) {
      int col = bn + wn + j * 8 + tg * 2;
      float b0 = bias ? bias[col] : 0.f;
      float b1 = bias ? bias[col + 1] : 0.f;
      float2 v0 = {c[i][j][0] + b0, c[i][j][1] + b1};
      float2 v1 = {c[i][j][2] + b0, c[i][j][3] + b1};
      *(float2*)&C[(size_t)r0 * N + col] = v0;
      *(float2*)&C[(size_t)(r0 + 8) * N + col] = v1;
    }
  }
}

// =================================================================
// Fused attention per (b, h, 64-row n-tile), tf32 mma for QK^T and PV
// =================================================================
#define QS_OFF  0
#define KS_OFF  (64 * 68)
#define VT_OFF  (KS_OFF + 256 * 68)
#define PS_OFF  (VT_OFF + 64 * 264)
#define ATTN_SMEM_WORDS (PS_OFF + 64 * 260)
#define ATTN_SMEM_BYTES (ATTN_SMEM_WORDS * 4)

__global__ __launch_bounds__(256, 1) void attn_kernel() {
  extern __shared__ uint32_t sm[];
  uint32_t* Qs = sm + QS_OFF;     // [n][d]  stride 68
  uint32_t* Ks = sm + KS_OFF;     // [m][d]  stride 68
  uint32_t* Vt = sm + VT_OFF;     // [d][m]  stride 264
  float*    Ps = (float*)(sm + PS_OFF);  // [n][m] stride 260
  uint32_t* PsU = sm + PS_OFF;

  int t = threadIdx.x;
  int b = blockIdx.y >> 3, h = blockIdx.y & 7;
  int n0 = blockIdx.x * 64;
  int w = t >> 5, l = t & 31;
  int g = l >> 2, tg = l & 3;

  const float* qkvb = g_qkv + (size_t)b * NSEQ * QKV3 + h * DH;

  {
    int c16 = t & 15, r16 = t >> 4;
    int d0 = c16 * 4;
    #pragma unroll
    for (int i = 0; i < 16; ++i) {
      int m = r16 + i * 16;
      const float* rowp = qkvb + (size_t)m * QKV3;
      float4 k4 = *(const float4*)(rowp + DIMC + d0);
      uint4 ku = {f2tf(k4.x), f2tf(k4.y), f2tf(k4.z), f2tf(k4.w)};
      *(uint4*)&Ks[m * 68 + d0] = ku;
      float4 v4 = *(const float4*)(rowp + 2 * DIMC + d0);
      Vt[(d0 + 0) * 264 + m] = f2tf(v4.x);
      Vt[(d0 + 1) * 264 + m] = f2tf(v4.y);
      Vt[(d0 + 2) * 264 + m] = f2tf(v4.z);
      Vt[(d0 + 3) * 264 + m] = f2tf(v4.w);
    }
    #pragma unroll
    for (int i = 0; i < 4; ++i) {
      int n = r16 + i * 16;
      const float* rowp = qkvb + (size_t)(n0 + n) * QKV3;
      float4 q4 = *(const float4*)(rowp + d0);
      uint4 qu = {f2tf(q4.x), f2tf(q4.y), f2tf(q4.z), f2tf(q4.w)};
      *(uint4*)&Qs[n * 68 + d0] = qu;
    }
  }
  __syncthreads();

  // scores S[64][256] = Q @ K^T ; warp tile 32x64
  {
    int wm = (w >> 2) * 32;
    int wnn = (w & 3) * 64;
    float s[2][8][4];
    #pragma unroll
    for (int i = 0; i < 2; ++i)
      #pragma unroll
      for (int j = 0; j < 8; ++j)
        #pragma unroll
        for (int q = 0; q < 4; ++q) s[i][j][q] = 0.f;

    #pragma unroll
    for (int kk = 0; kk < 64; kk += 8) {
      uint32_t a[2][4], bf[8][2];
      #pragma unroll
      for (int i = 0; i < 2; ++i) {
        int r0 = wm + i * 16;
        a[i][0] = Qs[(r0 + g) * 68 + kk + tg];
        a[i][1] = Qs[(r0 + g + 8) * 68 + kk + tg];
        a[i][2] = Qs[(r0 + g) * 68 + kk + tg + 4];
        a[i][3] = Qs[(r0 + g + 8) * 68 + kk + tg + 4];
      }
      #pragma unroll
      for (int j = 0; j < 8; ++j) {
        int m0 = wnn + j * 8;
        bf[j][0] = Ks[(m0 + g) * 68 + kk + tg];
        bf[j][1] = Ks[(m0 + g) * 68 + kk + tg + 4];
      }
      #pragma unroll
      for (int i = 0; i < 2; ++i)
        #pragma unroll
        for (int j = 0; j < 8; ++j)
          mma_tf32(s[i][j], a[i][0], a[i][1], a[i][2], a[i][3],
                   bf[j][0], bf[j][1]);
    }
    #pragma unroll
    for (int i = 0; i < 2; ++i) {
      int r0 = wm + i * 16 + g;
      #pragma unroll
      for (int j = 0; j < 8; ++j) {
        int cc = wnn + j * 8 + tg * 2;
        Ps[r0 * 260 + cc]           = s[i][j][0] * SCALE;
        Ps[r0 * 260 + cc + 1]       = s[i][j][1] * SCALE;
        Ps[(r0 + 8) * 260 + cc]     = s[i][j][2] * SCALE;
        Ps[(r0 + 8) * 260 + cc + 1] = s[i][j][3] * SCALE;
      }
    }
  }
  __syncthreads();

  // softmax; fp32 attn -> g_attn, tf32 bits -> Ps in place
  {
    #pragma unroll
    for (int r = 0; r < 8; ++r) {
      int n = w * 8 + r;
      float* row = &Ps[n * 260];
      float vals[8];
      float vmax = -1e30f;
      #pragma unroll
      for (int i = 0; i < 8; ++i) {
        vals[i] = row[l + i * 32];
        vmax = fmaxf(vmax, vals[i]);
      }
      #pragma unroll
      for (int o = 16; o; o >>= 1)
        vmax = fmaxf(vmax, __shfl_xor_sync(0xffffffffu, vmax, o));
      float ssum = 0.f;
      #pragma unroll
      for (int i = 0; i < 8; ++i) { vals[i] = __expf(vals[i] - vmax); ssum += vals[i]; }
      #pragma unroll
      for (int o = 16; o; o >>= 1) ssum += __shfl_xor_sync(0xffffffffu, ssum, o);
      float inv = 1.f / ssum;
      float* gA = &g_attn[((size_t)(b * 8 + h) * 256 + n0 + n) * 256];
      #pragma unroll
      for (int i = 0; i < 8; ++i) {
        float a = vals[i] * inv;
        gA[l + i * 32] = a;
        PsU[n * 260 + l + i * 32] = f2tf(a);
      }
    }
  }
  __syncthreads();

  // O[64][64] = P @ V ; warp tile 32x16
  {
    int wm = (w >> 2) * 32;
    int wd = (w & 3) * 16;
    float oc[2][2][4];
    #pragma unroll
    for (int i = 0; i < 2; ++i)
      #pragma unroll
      for (int j = 0; j < 2; ++j)
        #pragma unroll
        for (int q = 0; q < 4; ++q) oc[i][j][q] = 0.f;

    #pragma unroll 4
    for (int kk = 0; kk < 256; kk += 8) {
      uint32_t a[2][4], bf[2][2];
      #pragma unroll
      for (int i = 0; i < 2; ++i) {
        int r0 = wm + i * 16;
        a[i][0] = PsU[(r0 + g) * 260 + kk + tg];
        a[i][1] = PsU[(r0 + g + 8) * 260 + kk + tg];
        a[i][2] = PsU[(r0 + g) * 260 + kk + tg + 4];
        a[i][3] = PsU[(r0 + g + 8) * 260 + kk + tg + 4];
      }
      #pragma unroll
      for (int j = 0; j < 2; ++j) {
        int d0 = wd + j * 8;
        bf[j][0] = Vt[(d0 + g) * 264 + kk + tg];
        bf[j][1] = Vt[(d0 + g) * 264 + kk + tg + 4];
      }
      #pragma unroll
      for (int i = 0; i < 2; ++i)
        #pragma unroll
        for (int j = 0; j < 2; ++j)
          mma_tf32(oc[i][j], a[i][0], a[i][1], a[i][2], a[i][3],
                   bf[j][0], bf[j][1]);
    }
    #pragma unroll
    for (int i = 0; i < 2; ++i) {
      int n = n0 + wm + i * 16 + g;
      #pragma unroll
      for (int j = 0; j < 2; ++j) {
        int dd = h * 64 + wd + j * 8 + tg * 2;
        float2 v0 = {oc[i][j][0], oc[i][j][1]};
        float2 v1 = {oc[i][j][2], oc[i][j][3]};
        *(float2*)&g_o[(size_t)(b * 256 + n) * 512 + dd] = v0;
        *(float2*)&g_o[(size_t)(b * 256 + n + 8) * 512 + dd] = v1;
      }
    }
  }
}

// =================================================================
// rpos v3 (tensor cores): per (n,h) block
//   C[16x64] = A[16x256] @ B[256x64]
//   A rows 0..7 = attn[b=0..7][h][n][:], rows 8..15 zero
//   B = gathered table rows idx[n,m], head slice, staged [m][d]
// smem 87KB -> occupancy 2
// =================================================================
#define RP_IDX_OFF 0
#define RP_A_OFF   256
#define RP_T_OFF   (RP_A_OFF + 16 * 260)
#define RP_SMEM_WORDS (RP_T_OFF + 256 * 68)
#define RP_SMEM_BYTES (RP_SMEM_WORDS * 4)

__global__ __launch_bounds__(256) void rpos_kernel(
    const float* __restrict__ table, const int* __restrict__ idx_map) {
  extern __shared__ uint32_t rsm[];
  int* sIdx = (int*)(rsm + RP_IDX_OFF);
  uint32_t* sA = rsm + RP_A_OFF;   // [16][260]
  uint32_t* sT = rsm + RP_T_OFF;   // [256][68]

  int n = blockIdx.x, h = blockIdx.y;
  int t = threadIdx.x;
  int w = t >> 5, l = t & 31;
  int g = l >> 2, tg = l & 3;

  sIdx[t] = idx_map[n * 256 + t];
  __syncwarp();

  // stage attn rows (tf32) + zero padding
  #pragma unroll
  for (int b = 0; b < 8; ++b)
    sA[b * 260 + t] = f2tf(g_attn[((size_t)(b * 8 + h) * 256 + n) * 256 + t]);
  #pragma unroll
  for (int b = 8; b < 16; ++b)
    sA[b * 260 + t] = 0u;

  // gather table rows (warp w owns m in [w*32, w*32+32)), 4-deep pipeline
  {
    const float* tb = table + h * DH + 2 * l;
    int base = w * 32;
    float2 pre[4];
    #pragma unroll
    for (int i = 0; i < 4; ++i)
      pre[i] = *(const float2*)&tb[(size_t)sIdx[base + i] * DIMC];
    #pragma unroll
    for (int i = 0; i < 32; ++i) {
      float2 v = pre[i & 3];
      if (i + 4 < 32)
        pre[i & 3] = *(const float2*)&tb[(size_t)sIdx[base + i + 4] * DIMC];
      uint32_t* dst = &sT[(base + i) * 68 + 2 * l];
      dst[0] = f2tf(v.x);
      dst[1] = f2tf(v.y);
    }
  }
  __syncthreads();

  // mma: each warp owns 8 d-columns (wd = w*8)
  int wd = w * 8;
  float c[4] = {0.f, 0.f, 0.f, 0.f};
  #pragma unroll
  for (int kk = 0; kk < 256; kk += 8) {
    uint32_t a0 = sA[g * 260 + kk + tg];
    uint32_t a1 = sA[(g + 8) * 260 + kk + tg];
    uint32_t a2 = sA[g * 260 + kk + tg + 4];
    uint32_t a3 = sA[(g + 8) * 260 + kk + tg + 4];
    uint32_t b0 = sT[(kk + tg) * 68 + wd + g];
    uint32_t b1 = sT[(kk + tg + 4) * 68 + wd + g];
    mma_tf32(c, a0, a1, a2, a3, b0, b1);
  }

  // accumulate into g_o: row g = batch, cols wd + tg*2, tg*2+1
  {
    float* dst = &g_o[((size_t)(g * 256 + n)) * 512 + h * 64 + wd + tg * 2];
    dst[0] += c[0];
    dst[1] += c[1];
  }
}

// =================================================================
extern "C" void kernel_launch(void* const* d_in, const int* in_sizes, int n_in,
                              void* d_out, int out_size) {
  const float* x      = (const float*)d_in[0];
  const float* ln_g   = (const float*)d_in[1];
  const float* ln_b   = (const float*)d_in[2];
  const float* w_qkv  = (const float*)d_in[3];
  const float* table  = (const float*)d_in[4];
  const float* w_out  = (const float*)d_in[5];
  const float* b_out  = (const float*)d_in[6];
  const int*   idxmap = (const int*)d_in[7];
  float* out = (float*)d_out;

  cudaFuncSetAttribute(attn_kernel, cudaFuncAttributeMaxDynamicSharedMemorySize,
                       ATTN_SMEM_BYTES);
  cudaFuncSetAttribute(rpos_kernel, cudaFuncAttributeMaxDynamicSharedMemorySize,
                       RP_SMEM_BYTES);

  void *p_qkv, *p_o;
  cudaGetSymbolAddress(&p_qkv, g_qkv);
  cudaGetSymbolAddress(&p_o, g_o);

  // 1. LN row stats
  ln_stats_kernel<<<NTOK / 8, 256>>>(x);

  // 2. qkv = LN(x) @ w_qkv   (2048 x 1536 x 512), fused LN, BN=128
  gemm_tf32<128, 2, 4, true><<<dim3(QKV3 / 128, NTOK / 128), 256>>>(
      x, w_qkv, nullptr, (float*)p_qkv, ln_g, ln_b, NTOK, QKV3, DIMC);

  // 3. attention (scores, softmax, attn·V) on tensor cores
  attn_kernel<<<dim3(4, NB * NHEADS), 256, ATTN_SMEM_BYTES>>>();

  // 4. relative-position contribution (tensor-core gather GEMM)
  rpos_kernel<<<dim3(NSEQ, NHEADS), 256, RP_SMEM_BYTES>>>(table, idxmap);

  // 5. out = g_o @ w_out + b_out   (2048 x 512 x 512), BN=64
  gemm_tf32<64, 4, 2, false><<<dim3(DIMC / 64, NTOK / 128), 256>>>(
      (const float*)p_o, w_out, b_out, out, nullptr, nullptr, NTOK, DIMC, DIMC);
}

// round 5
// speedup vs baseline: 1.2296x; 1.2296x over previous
#include <cuda_runtime.h>
#include <math.h>
#include <stdint.h>

#define NB      8
#define NSEQ    256
#define DIMC    512
#define NHEADS  8
#define DH      64
#define NTOK    (NB * NSEQ)       // 2048
#define QKV3    (3 * DIMC)        // 1536
#define SCALE   0.125f            // 64^-0.5

// ---------------- scratch (no cudaMalloc allowed) ----------------
__device__ float g_xn[NTOK * DIMC];                      // 4 MB
__device__ float g_qkv[NTOK * QKV3];                     // 12.6 MB
__device__ float g_attn[NB * NHEADS * NSEQ * NSEQ];      // 16.8 MB  [b][h][n][m]
__device__ float g_o[NTOK * DIMC];                       // 4 MB     [b][n][h*64+d]

// ---------------- tf32 mma helpers ----------------
__device__ __forceinline__ uint32_t f2tf(float x) {
  uint32_t r;
  asm("cvt.rna.tf32.f32 %0, %1;" : "=r"(r) : "f"(x));
  return r;
}

__device__ __forceinline__ void mma_tf32(float c[4],
    uint32_t a0, uint32_t a1, uint32_t a2, uint32_t a3,
    uint32_t b0, uint32_t b1) {
  asm volatile(
    "mma.sync.aligned.m16n8k8.row.col.f32.tf32.tf32.f32 "
    "{%0,%1,%2,%3}, {%4,%5,%6,%7}, {%8,%9}, {%0,%1,%2,%3};\n"
    : "+f"(c[0]), "+f"(c[1]), "+f"(c[2]), "+f"(c[3])
    : "r"(a0), "r"(a1), "r"(a2), "r"(a3), "r"(b0), "r"(b1));
}

// =================================================================
// LayerNorm: one block per (b,n) row, 256 threads, 2 elems/thread
// =================================================================
__global__ void ln_kernel(const float* __restrict__ x,
                          const float* __restrict__ gamma,
                          const float* __restrict__ beta) {
  int row = blockIdx.x;
  int t = threadIdx.x;
  const float* xr = x + (size_t)row * DIMC;
  float v0 = xr[t], v1 = xr[t + 256];

  __shared__ float red[8];
  __shared__ float stat;

  float s = v0 + v1;
  #pragma unroll
  for (int o = 16; o; o >>= 1) s += __shfl_xor_sync(0xffffffffu, s, o);
  if ((t & 31) == 0) red[t >> 5] = s;
  __syncthreads();
  if (t < 32) {
    float z = (t < 8) ? red[t] : 0.f;
    #pragma unroll
    for (int o = 4; o; o >>= 1) z += __shfl_xor_sync(0xffffffffu, z, o);
    if (t == 0) stat = z * (1.f / DIMC);
  }
  __syncthreads();
  float mean = stat;
  __syncthreads();

  float d0 = v0 - mean, d1 = v1 - mean;
  float vs = d0 * d0 + d1 * d1;
  #pragma unroll
  for (int o = 16; o; o >>= 1) vs += __shfl_xor_sync(0xffffffffu, vs, o);
  if ((t & 31) == 0) red[t >> 5] = vs;
  __syncthreads();
  if (t < 32) {
    float z = (t < 8) ? red[t] : 0.f;
    #pragma unroll
    for (int o = 4; o; o >>= 1) z += __shfl_xor_sync(0xffffffffu, z, o);
    if (t == 0) stat = rsqrtf(z * (1.f / DIMC) + 1e-5f);
  }
  __syncthreads();
  float inv = stat;

  float* xo = g_xn + (size_t)row * DIMC;
  xo[t]       = d0 * inv * gamma[t]       + beta[t];
  xo[t + 256] = d1 * inv * gamma[t + 256] + beta[t + 256];
}

// =================================================================
// tf32 tensor-core GEMM v2: C[M,N] = A[M,K] @ B[K,N] (+bias)
// BM=128, BN template (128 or 64), BK=16, 256 threads,
// double-buffered smem, reg-prefetched global loads, 1 sync/iter.
// =================================================================
template<int BN, int WARPS_M, int WARPS_N>
__global__ __launch_bounds__(256) void gemm_tf32(
    const float* __restrict__ A, const float* __restrict__ B,
    const float* __restrict__ bias, float* __restrict__ C,
    int M, int N, int K) {
  constexpr int BM = 128, BK = 16;
  constexpr int WTM = BM / WARPS_M;
  constexpr int WTN = BN / WARPS_N;
  constexpr int MI = WTM / 16;
  constexpr int NI = WTN / 8;
  constexpr int AS = BK + 4;     // 20 words, conflict-free for A frags
  constexpr int BS = BN + 4;     // conflict-free for B frags
  constexpr int BF4 = (BK * BN) / (256 * 4);  // float4 per thread for B

  __shared__ uint32_t As[2][BM * AS];
  __shared__ uint32_t Bs[2][BK * BS];

  int t = threadIdx.x;
  int w = t >> 5, l = t & 31;
  int g = l >> 2, tg = l & 3;
  int wm = (w % WARPS_M) * WTM;
  int wn = (w / WARPS_M) * WTN;
  int bm = blockIdx.y * BM, bn = blockIdx.x * BN;

  int arow = t >> 1, akh = (t & 1) * 8;
  const float* Aptr = A + (size_t)(bm + arow) * K + akh;

  int brow[BF4], bcol[BF4];
  #pragma unroll
  for (int j = 0; j < BF4; ++j) {
    int lin = (j * 256 + t) * 4;
    brow[j] = lin / BN;
    bcol[j] = lin % BN;
  }

  float c[MI][NI][4];
  #pragma unroll
  for (int i = 0; i < MI; ++i)
    #pragma unroll
    for (int j = 0; j < NI; ++j)
      #pragma unroll
      for (int q = 0; q < 4; ++q) c[i][j][q] = 0.f;

  float4 av0, av1, bv[BF4];

  // prologue: tile 0 -> buffer 0
  av0 = *(const float4*)(Aptr);
  av1 = *(const float4*)(Aptr + 4);
  #pragma unroll
  for (int j = 0; j < BF4; ++j)
    bv[j] = *(const float4*)(B + (size_t)brow[j] * N + bn + bcol[j]);
  {
    uint32_t* as = As[0] + arow * AS + akh;
    as[0]=f2tf(av0.x); as[1]=f2tf(av0.y); as[2]=f2tf(av0.z); as[3]=f2tf(av0.w);
    as[4]=f2tf(av1.x); as[5]=f2tf(av1.y); as[6]=f2tf(av1.z); as[7]=f2tf(av1.w);
    #pragma unroll
    for (int j = 0; j < BF4; ++j) {
      uint32_t* bs = Bs[0] + brow[j] * BS + bcol[j];
      bs[0]=f2tf(bv[j].x); bs[1]=f2tf(bv[j].y); bs[2]=f2tf(bv[j].z); bs[3]=f2tf(bv[j].w);
    }
  }
  __syncthreads();

  int nk = K / BK;
  for (int it = 0; it < nk; ++it) {
    int buf = it & 1;
    bool more = (it + 1 < nk);
    if (more) {
      int k0 = (it + 1) * BK;
      av0 = *(const float4*)(Aptr + k0);
      av1 = *(const float4*)(Aptr + k0 + 4);
      #pragma unroll
      for (int j = 0; j < BF4; ++j)
        bv[j] = *(const float4*)(B + (size_t)(k0 + brow[j]) * N + bn + bcol[j]);
    }

    #pragma unroll
    for (int kk = 0; kk < BK; kk += 8) {
      uint32_t af[MI][4], bf[NI][2];
      #pragma unroll
      for (int i = 0; i < MI; ++i) {
        const uint32_t* p = As[buf] + (wm + i * 16 + g) * AS + kk + tg;
        af[i][0] = p[0];
        af[i][1] = p[8 * AS];
        af[i][2] = p[4];
        af[i][3] = p[8 * AS + 4];
      }
      #pragma unroll
      for (int j = 0; j < NI; ++j) {
        const uint32_t* p = Bs[buf] + (kk + tg) * BS + wn + j * 8 + g;
        bf[j][0] = p[0];
        bf[j][1] = p[4 * BS];
      }
      #pragma unroll
      for (int i = 0; i < MI; ++i)
        #pragma unroll
        for (int j = 0; j < NI; ++j)
          mma_tf32(c[i][j], af[i][0], af[i][1], af[i][2], af[i][3],
                   bf[j][0], bf[j][1]);
    }

    if (more) {
      int nb = buf ^ 1;
      uint32_t* as = As[nb] + arow * AS + akh;
      as[0]=f2tf(av0.x); as[1]=f2tf(av0.y); as[2]=f2tf(av0.z); as[3]=f2tf(av0.w);
      as[4]=f2tf(av1.x); as[5]=f2tf(av1.y); as[6]=f2tf(av1.z); as[7]=f2tf(av1.w);
      #pragma unroll
      for (int j = 0; j < BF4; ++j) {
        uint32_t* bs = Bs[nb] + brow[j] * BS + bcol[j];
        bs[0]=f2tf(bv[j].x); bs[1]=f2tf(bv[j].y); bs[2]=f2tf(bv[j].z); bs[3]=f2tf(bv[j].w);
      }
    }
    __syncthreads();
  }

  #pragma unroll
  for (int i = 0; i < MI; ++i) {
    int r0 = bm + wm + i * 16 + g;
    #pragma unroll
    for (int j = 0; j < NI; ++j) {
      int col = bn + wn + j * 8 + tg * 2;
      float b0 = bias ? bias[col] : 0.f;
      float b1 = bias ? bias[col + 1] : 0.f;
      float2 v0 = {c[i][j][0] + b0, c[i][j][1] + b1};
      float2 v1 = {c[i][j][2] + b0, c[i][j][3] + b1};
      *(float2*)&C[(size_t)r0 * N + col] = v0;
      *(float2*)&C[(size_t)(r0 + 8) * N + col] = v1;
    }
  }
}

// =================================================================
// Fused attention per (b, h, 64-row n-tile), tf32 mma for QK^T and PV
// =================================================================
#define QS_OFF  0
#define KS_OFF  (64 * 68)
#define VT_OFF  (KS_OFF + 256 * 68)
#define PS_OFF  (VT_OFF + 64 * 264)
#define ATTN_SMEM_WORDS (PS_OFF + 64 * 260)
#define ATTN_SMEM_BYTES (ATTN_SMEM_WORDS * 4)

__global__ __launch_bounds__(256, 1) void attn_kernel() {
  extern __shared__ uint32_t sm[];
  uint32_t* Qs = sm + QS_OFF;     // [n][d]  stride 68
  uint32_t* Ks = sm + KS_OFF;     // [m][d]  stride 68
  uint32_t* Vt = sm + VT_OFF;     // [d][m]  stride 264
  float*    Ps = (float*)(sm + PS_OFF);  // [n][m] stride 260
  uint32_t* PsU = sm + PS_OFF;

  int t = threadIdx.x;
  int b = blockIdx.y >> 3, h = blockIdx.y & 7;
  int n0 = blockIdx.x * 64;
  int w = t >> 5, l = t & 31;
  int g = l >> 2, tg = l & 3;

  const float* qkvb = g_qkv + (size_t)b * NSEQ * QKV3 + h * DH;

  {
    int c16 = t & 15, r16 = t >> 4;
    int d0 = c16 * 4;
    #pragma unroll
    for (int i = 0; i < 16; ++i) {
      int m = r16 + i * 16;
      const float* rowp = qkvb + (size_t)m * QKV3;
      float4 k4 = *(const float4*)(rowp + DIMC + d0);
      uint4 ku = {f2tf(k4.x), f2tf(k4.y), f2tf(k4.z), f2tf(k4.w)};
      *(uint4*)&Ks[m * 68 + d0] = ku;
      float4 v4 = *(const float4*)(rowp + 2 * DIMC + d0);
      Vt[(d0 + 0) * 264 + m] = f2tf(v4.x);
      Vt[(d0 + 1) * 264 + m] = f2tf(v4.y);
      Vt[(d0 + 2) * 264 + m] = f2tf(v4.z);
      Vt[(d0 + 3) * 264 + m] = f2tf(v4.w);
    }
    #pragma unroll
    for (int i = 0; i < 4; ++i) {
      int n = r16 + i * 16;
      const float* rowp = qkvb + (size_t)(n0 + n) * QKV3;
      float4 q4 = *(const float4*)(rowp + d0);
      uint4 qu = {f2tf(q4.x), f2tf(q4.y), f2tf(q4.z), f2tf(q4.w)};
      *(uint4*)&Qs[n * 68 + d0] = qu;
    }
  }
  __syncthreads();

  // scores S[64][256] = Q @ K^T ; warp tile 32x64
  {
    int wm = (w >> 2) * 32;
    int wnn = (w & 3) * 64;
    float s[2][8][4];
    #pragma unroll
    for (int i = 0; i < 2; ++i)
      #pragma unroll
      for (int j = 0; j < 8; ++j)
        #pragma unroll
        for (int q = 0; q < 4; ++q) s[i][j][q] = 0.f;

    #pragma unroll
    for (int kk = 0; kk < 64; kk += 8) {
      uint32_t a[2][4], bf[8][2];
      #pragma unroll
      for (int i = 0; i < 2; ++i) {
        int r0 = wm + i * 16;
        a[i][0] = Qs[(r0 + g) * 68 + kk + tg];
        a[i][1] = Qs[(r0 + g + 8) * 68 + kk + tg];
        a[i][2] = Qs[(r0 + g) * 68 + kk + tg + 4];
        a[i][3] = Qs[(r0 + g + 8) * 68 + kk + tg + 4];
      }
      #pragma unroll
      for (int j = 0; j < 8; ++j) {
        int m0 = wnn + j * 8;
        bf[j][0] = Ks[(m0 + g) * 68 + kk + tg];
        bf[j][1] = Ks[(m0 + g) * 68 + kk + tg + 4];
      }
      #pragma unroll
      for (int i = 0; i < 2; ++i)
        #pragma unroll
        for (int j = 0; j < 8; ++j)
          mma_tf32(s[i][j], a[i][0], a[i][1], a[i][2], a[i][3],
                   bf[j][0], bf[j][1]);
    }
    #pragma unroll
    for (int i = 0; i < 2; ++i) {
      int r0 = wm + i * 16 + g;
      #pragma unroll
      for (int j = 0; j < 8; ++j) {
        int cc = wnn + j * 8 + tg * 2;
        Ps[r0 * 260 + cc]           = s[i][j][0] * SCALE;
        Ps[r0 * 260 + cc + 1]       = s[i][j][1] * SCALE;
        Ps[(r0 + 8) * 260 + cc]     = s[i][j][2] * SCALE;
        Ps[(r0 + 8) * 260 + cc + 1] = s[i][j][3] * SCALE;
      }
    }
  }
  __syncthreads();

  // softmax; fp32 attn -> g_attn, tf32 bits -> Ps in place
  {
    #pragma unroll
    for (int r = 0; r < 8; ++r) {
      int n = w * 8 + r;
      float* row = &Ps[n * 260];
      float vals[8];
      float vmax = -1e30f;
      #pragma unroll
      for (int i = 0; i < 8; ++i) {
        vals[i] = row[l + i * 32];
        vmax = fmaxf(vmax, vals[i]);
      }
      #pragma unroll
      for (int o = 16; o; o >>= 1)
        vmax = fmaxf(vmax, __shfl_xor_sync(0xffffffffu, vmax, o));
      float ssum = 0.f;
      #pragma unroll
      for (int i = 0; i < 8; ++i) { vals[i] = __expf(vals[i] - vmax); ssum += vals[i]; }
      #pragma unroll
      for (int o = 16; o; o >>= 1) ssum += __shfl_xor_sync(0xffffffffu, ssum, o);
      float inv = 1.f / ssum;
      float* gA = &g_attn[((size_t)(b * 8 + h) * 256 + n0 + n) * 256];
      #pragma unroll
      for (int i = 0; i < 8; ++i) {
        float a = vals[i] * inv;
        gA[l + i * 32] = a;
        PsU[n * 260 + l + i * 32] = f2tf(a);
      }
    }
  }
  __syncthreads();

  // O[64][64] = P @ V ; warp tile 32x16
  {
    int wm = (w >> 2) * 32;
    int wd = (w & 3) * 16;
    float oc[2][2][4];
    #pragma unroll
    for (int i = 0; i < 2; ++i)
      #pragma unroll
      for (int j = 0; j < 2; ++j)
        #pragma unroll
        for (int q = 0; q < 4; ++q) oc[i][j][q] = 0.f;

    #pragma unroll 4
    for (int kk = 0; kk < 256; kk += 8) {
      uint32_t a[2][4], bf[2][2];
      #pragma unroll
      for (int i = 0; i < 2; ++i) {
        int r0 = wm + i * 16;
        a[i][0] = PsU[(r0 + g) * 260 + kk + tg];
        a[i][1] = PsU[(r0 + g + 8) * 260 + kk + tg];
        a[i][2] = PsU[(r0 + g) * 260 + kk + tg + 4];
        a[i][3] = PsU[(r0 + g + 8) * 260 + kk + tg + 4];
      }
      #pragma unroll
      for (int j = 0; j < 2; ++j) {
        int d0 = wd + j * 8;
        bf[j][0] = Vt[(d0 + g) * 264 + kk + tg];
        bf[j][1] = Vt[(d0 + g) * 264 + kk + tg + 4];
      }
      #pragma unroll
      for (int i = 0; i < 2; ++i)
        #pragma unroll
        for (int j = 0; j < 2; ++j)
          mma_tf32(oc[i][j], a[i][0], a[i][1], a[i][2], a[i][3],
                   bf[j][0], bf[j][1]);
    }
    #pragma unroll
    for (int i = 0; i < 2; ++i) {
      int n = n0 + wm + i * 16 + g;
      #pragma unroll
      for (int j = 0; j < 2; ++j) {
        int dd = h * 64 + wd + j * 8 + tg * 2;
        float2 v0 = {oc[i][j][0], oc[i][j][1]};
        float2 v1 = {oc[i][j][2], oc[i][j][3]};
        *(float2*)&g_o[(size_t)(b * 256 + n) * 512 + dd] = v0;
        *(float2*)&g_o[(size_t)(b * 256 + n + 8) * 512 + dd] = v1;
      }
    }
  }
}

// =================================================================
// rpos v4: out2[b,h,n,d] += Σ_m attn[b,h,n,m] * T[idx[n,m], h*64+d]
// Lane owns 4 d-cols (LDG.128/row); half-warps split m; 4-deep prefetch.
// =================================================================
__global__ __launch_bounds__(256) void rpos_kernel(
    const float* __restrict__ table, const int* __restrict__ idx_map) {
  int n = blockIdx.x, h = blockIdx.y;
  __shared__ float sA[8][256];
  __shared__ int   sIdx[256];
  __shared__ float sPart[8][8][64];  // [warp][b][d]

  int t = threadIdx.x;
  sIdx[t] = idx_map[n * 256 + t];
  #pragma unroll
  for (int b = 0; b < 8; ++b)
    sA[b][t] = g_attn[((size_t)(b * 8 + h) * 256 + n) * 256 + t];
  __syncthreads();

  int w = t >> 5, l = t & 31;
  int hw = l >> 4, dl = l & 15;     // d = dl*4
  int base = w * 32 + hw;           // this thread's m = base + 2*i

  float acc[8][4];
  #pragma unroll
  for (int b = 0; b < 8; ++b)
    #pragma unroll
    for (int q = 0; q < 4; ++q) acc[b][q] = 0.f;

  const float* tb = table + h * DH + dl * 4;

  float4 buf[4];
  #pragma unroll
  for (int i = 0; i < 4; ++i)
    buf[i] = *(const float4*)&tb[(size_t)sIdx[base + 2 * i] * DIMC];

  #pragma unroll
  for (int i = 0; i < 16; ++i) {
    float4 tv = buf[i & 3];
    if (i + 4 < 16)
      buf[i & 3] = *(const float4*)&tb[(size_t)sIdx[base + 2 * (i + 4)] * DIMC];
    int m = base + 2 * i;
    #pragma unroll
    for (int b = 0; b < 8; ++b) {
      float a = sA[b][m];
      acc[b][0] += a * tv.x;
      acc[b][1] += a * tv.y;
      acc[b][2] += a * tv.z;
      acc[b][3] += a * tv.w;
    }
  }

  // combine the two half-warps (same d, complementary m)
  #pragma unroll
  for (int b = 0; b < 8; ++b)
    #pragma unroll
    for (int q = 0; q < 4; ++q)
      acc[b][q] += __shfl_xor_sync(0xffffffffu, acc[b][q], 16);

  if (hw == 0) {
    #pragma unroll
    for (int b = 0; b < 8; ++b) {
      float4 v = {acc[b][0], acc[b][1], acc[b][2], acc[b][3]};
      *(float4*)&sPart[w][b][dl * 4] = v;
    }
  }
  __syncthreads();

  #pragma unroll
  for (int o = t; o < 512; o += 256) {
    int b = o >> 6, d = o & 63;
    float s2 = 0.f;
    #pragma unroll
    for (int w2 = 0; w2 < 8; ++w2) s2 += sPart[w2][b][d];
    g_o[(size_t)(b * 256 + n) * 512 + h * 64 + d] += s2;
  }
}

// =================================================================
extern "C" void kernel_launch(void* const* d_in, const int* in_sizes, int n_in,
                              void* d_out, int out_size) {
  const float* x      = (const float*)d_in[0];
  const float* ln_g   = (const float*)d_in[1];
  const float* ln_b   = (const float*)d_in[2];
  const float* w_qkv  = (const float*)d_in[3];
  const float* table  = (const float*)d_in[4];
  const float* w_out  = (const float*)d_in[5];
  const float* b_out  = (const float*)d_in[6];
  const int*   idxmap = (const int*)d_in[7];
  float* out = (float*)d_out;

  cudaFuncSetAttribute(attn_kernel, cudaFuncAttributeMaxDynamicSharedMemorySize,
                       ATTN_SMEM_BYTES);

  void *p_xn, *p_qkv, *p_o;
  cudaGetSymbolAddress(&p_xn, g_xn);
  cudaGetSymbolAddress(&p_qkv, g_qkv);
  cudaGetSymbolAddress(&p_o, g_o);

  // 1. LayerNorm
  ln_kernel<<<NTOK, 256>>>(x, ln_g, ln_b);

  // 2. qkv = xn @ w_qkv   (2048 x 1536 x 512), BN=128
  gemm_tf32<128, 2, 4><<<dim3(QKV3 / 128, NTOK / 128), 256>>>(
      (const float*)p_xn, w_qkv, nullptr, (float*)p_qkv, NTOK, QKV3, DIMC);

  // 3. attention (scores, softmax, attn·V) on tensor cores
  attn_kernel<<<dim3(4, NB * NHEADS), 256, ATTN_SMEM_BYTES>>>();

  // 4. relative-position contribution (wide pipelined gather)
  rpos_kernel<<<dim3(NSEQ, NHEADS), 256>>>(table, idxmap);

  // 5. out = g_o @ w_out + b_out   (2048 x 512 x 512), BN=64 -> 128 blocks
  gemm_tf32<64, 4, 2><<<dim3(DIMC / 64, NTOK / 128), 256>>>(
      (const float*)p_o, w_out, b_out, out, NTOK, DIMC, DIMC);
}

// round 6
// speedup vs baseline: 1.2501x; 1.0166x over previous
#include <cuda_runtime.h>
#include <math.h>
#include <stdint.h>

#define NB      8
#define NSEQ    256
#define DIMC    512
#define NHEADS  8
#define DH      64
#define NTOK    (NB * NSEQ)       // 2048
#define QKV3    (3 * DIMC)        // 1536
#define SCALE   0.125f            // 64^-0.5

// ---------------- scratch (no cudaMalloc allowed) ----------------
__device__ float g_xn[NTOK * DIMC];                      // 4 MB
__device__ float g_qkv[NTOK * QKV3];                     // 12.6 MB
__device__ float g_attn[NB * NHEADS * NSEQ * NSEQ];      // 16.8 MB  [b][h][n][m]
__device__ float g_o[NTOK * DIMC];                       // 4 MB     [b][n][h*64+d]

// ---------------- tf32 mma helpers ----------------
__device__ __forceinline__ uint32_t f2tf(float x) {
  uint32_t r;
  asm("cvt.rna.tf32.f32 %0, %1;" : "=r"(r) : "f"(x));
  return r;
}

__device__ __forceinline__ void mma_tf32(float c[4],
    uint32_t a0, uint32_t a1, uint32_t a2, uint32_t a3,
    uint32_t b0, uint32_t b1) {
  asm volatile(
    "mma.sync.aligned.m16n8k8.row.col.f32.tf32.tf32.f32 "
    "{%0,%1,%2,%3}, {%4,%5,%6,%7}, {%8,%9}, {%0,%1,%2,%3};\n"
    : "+f"(c[0]), "+f"(c[1]), "+f"(c[2]), "+f"(c[3])
    : "r"(a0), "r"(a1), "r"(a2), "r"(a3), "r"(b0), "r"(b1));
}

// =================================================================
// LayerNorm: one block per (b,n) row, 256 threads, 2 elems/thread
// =================================================================
__global__ void ln_kernel(const float* __restrict__ x,
                          const float* __restrict__ gamma,
                          const float* __restrict__ beta) {
  int row = blockIdx.x;
  int t = threadIdx.x;
  const float* xr = x + (size_t)row * DIMC;
  float v0 = xr[t], v1 = xr[t + 256];

  __shared__ float red[8];
  __shared__ float stat;

  float s = v0 + v1;
  #pragma unroll
  for (int o = 16; o; o >>= 1) s += __shfl_xor_sync(0xffffffffu, s, o);
  if ((t & 31) == 0) red[t >> 5] = s;
  __syncthreads();
  if (t < 32) {
    float z = (t < 8) ? red[t] : 0.f;
    #pragma unroll
    for (int o = 4; o; o >>= 1) z += __shfl_xor_sync(0xffffffffu, z, o);
    if (t == 0) stat = z * (1.f / DIMC);
  }
  __syncthreads();
  float mean = stat;
  __syncthreads();

  float d0 = v0 - mean, d1 = v1 - mean;
  float vs = d0 * d0 + d1 * d1;
  #pragma unroll
  for (int o = 16; o; o >>= 1) vs += __shfl_xor_sync(0xffffffffu, vs, o);
  if ((t & 31) == 0) red[t >> 5] = vs;
  __syncthreads();
  if (t < 32) {
    float z = (t < 8) ? red[t] : 0.f;
    #pragma unroll
    for (int o = 4; o; o >>= 1) z += __shfl_xor_sync(0xffffffffu, z, o);
    if (t == 0) stat = rsqrtf(z * (1.f / DIMC) + 1e-5f);
  }
  __syncthreads();
  float inv = stat;

  float* xo = g_xn + (size_t)row * DIMC;
  xo[t]       = d0 * inv * gamma[t]       + beta[t];
  xo[t + 256] = d1 * inv * gamma[t + 256] + beta[t + 256];
}

// =================================================================
// tf32 tensor-core GEMM v2: C[M,N] = A[M,K] @ B[K,N] (+bias)
// BM=128, BN template (128 or 64), BK=16, 256 threads,
// double-buffered smem, reg-prefetched global loads, 1 sync/iter.
// =================================================================
template<int BN, int WARPS_M, int WARPS_N>
__global__ __launch_bounds__(256) void gemm_tf32(
    const float* __restrict__ A, const float* __restrict__ B,
    const float* __restrict__ bias, float* __restrict__ C,
    int M, int N, int K) {
  constexpr int BM = 128, BK = 16;
  constexpr int WTM = BM / WARPS_M;
  constexpr int WTN = BN / WARPS_N;
  constexpr int MI = WTM / 16;
  constexpr int NI = WTN / 8;
  constexpr int AS = BK + 4;
  constexpr int BS = BN + 4;
  constexpr int BF4 = (BK * BN) / (256 * 4);

  __shared__ uint32_t As[2][BM * AS];
  __shared__ uint32_t Bs[2][BK * BS];

  int t = threadIdx.x;
  int w = t >> 5, l = t & 31;
  int g = l >> 2, tg = l & 3;
  int wm = (w % WARPS_M) * WTM;
  int wn = (w / WARPS_M) * WTN;
  int bm = blockIdx.y * BM, bn = blockIdx.x * BN;

  int arow = t >> 1, akh = (t & 1) * 8;
  const float* Aptr = A + (size_t)(bm + arow) * K + akh;

  int brow[BF4], bcol[BF4];
  #pragma unroll
  for (int j = 0; j < BF4; ++j) {
    int lin = (j * 256 + t) * 4;
    brow[j] = lin / BN;
    bcol[j] = lin % BN;
  }

  float c[MI][NI][4];
  #pragma unroll
  for (int i = 0; i < MI; ++i)
    #pragma unroll
    for (int j = 0; j < NI; ++j)
      #pragma unroll
      for (int q = 0; q < 4; ++q) c[i][j][q] = 0.f;

  float4 av0, av1, bv[BF4];

  av0 = *(const float4*)(Aptr);
  av1 = *(const float4*)(Aptr + 4);
  #pragma unroll
  for (int j = 0; j < BF4; ++j)
    bv[j] = *(const float4*)(B + (size_t)brow[j] * N + bn + bcol[j]);
  {
    uint32_t* as = As[0] + arow * AS + akh;
    as[0]=f2tf(av0.x); as[1]=f2tf(av0.y); as[2]=f2tf(av0.z); as[3]=f2tf(av0.w);
    as[4]=f2tf(av1.x); as[5]=f2tf(av1.y); as[6]=f2tf(av1.z); as[7]=f2tf(av1.w);
    #pragma unroll
    for (int j = 0; j < BF4; ++j) {
      uint32_t* bs = Bs[0] + brow[j] * BS + bcol[j];
      bs[0]=f2tf(bv[j].x); bs[1]=f2tf(bv[j].y); bs[2]=f2tf(bv[j].z); bs[3]=f2tf(bv[j].w);
    }
  }
  __syncthreads();

  int nk = K / BK;
  for (int it = 0; it < nk; ++it) {
    int buf = it & 1;
    bool more = (it + 1 < nk);
    if (more) {
      int k0 = (it + 1) * BK;
      av0 = *(const float4*)(Aptr + k0);
      av1 = *(const float4*)(Aptr + k0 + 4);
      #pragma unroll
      for (int j = 0; j < BF4; ++j)
        bv[j] = *(const float4*)(B + (size_t)(k0 + brow[j]) * N + bn + bcol[j]);
    }

    #pragma unroll
    for (int kk = 0; kk < BK; kk += 8) {
      uint32_t af[MI][4], bf[NI][2];
      #pragma unroll
      for (int i = 0; i < MI; ++i) {
        const uint32_t* p = As[buf] + (wm + i * 16 + g) * AS + kk + tg;
        af[i][0] = p[0];
        af[i][1] = p[8 * AS];
        af[i][2] = p[4];
        af[i][3] = p[8 * AS + 4];
      }
      #pragma unroll
      for (int j = 0; j < NI; ++j) {
        const uint32_t* p = Bs[buf] + (kk + tg) * BS + wn + j * 8 + g;
        bf[j][0] = p[0];
        bf[j][1] = p[4 * BS];
      }
      #pragma unroll
      for (int i = 0; i < MI; ++i)
        #pragma unroll
        for (int j = 0; j < NI; ++j)
          mma_tf32(c[i][j], af[i][0], af[i][1], af[i][2], af[i][3],
                   bf[j][0], bf[j][1]);
    }

    if (more) {
      int nb = buf ^ 1;
      uint32_t* as = As[nb] + arow * AS + akh;
      as[0]=f2tf(av0.x); as[1]=f2tf(av0.y); as[2]=f2tf(av0.z); as[3]=f2tf(av0.w);
      as[4]=f2tf(av1.x); as[5]=f2tf(av1.y); as[6]=f2tf(av1.z); as[7]=f2tf(av1.w);
      #pragma unroll
      for (int j = 0; j < BF4; ++j) {
        uint32_t* bs = Bs[nb] + brow[j] * BS + bcol[j];
        bs[0]=f2tf(bv[j].x); bs[1]=f2tf(bv[j].y); bs[2]=f2tf(bv[j].z); bs[3]=f2tf(bv[j].w);
      }
    }
    __syncthreads();
  }

  #pragma unroll
  for (int i = 0; i < MI; ++i) {
    int r0 = bm + wm + i * 16 + g;
    #pragma unroll
    for (int j = 0; j < NI; ++j) {
      int col = bn + wn + j * 8 + tg * 2;
      float b0 = bias ? bias[col] : 0.f;
      float b1 = bias ? bias[col + 1] : 0.f;
      float2 v0 = {c[i][j][0] + b0, c[i][j][1] + b1};
      float2 v1 = {c[i][j][2] + b0, c[i][j][3] + b1};
      *(float2*)&C[(size_t)r0 * N + col] = v0;
      *(float2*)&C[(size_t)(r0 + 8) * N + col] = v1;
    }
  }
}

// =================================================================
// Fused attention per (b, h, 64-row n-tile), tf32 mma, 512 threads
// (16 warps at occ 1 for latency hiding)
// =================================================================
#define QS_OFF  0
#define KS_OFF  (64 * 68)
#define VT_OFF  (KS_OFF + 256 * 68)
#define PS_OFF  (VT_OFF + 64 * 264)
#define ATTN_SMEM_WORDS (PS_OFF + 64 * 260)
#define ATTN_SMEM_BYTES (ATTN_SMEM_WORDS * 4)

__global__ __launch_bounds__(512, 1) void attn_kernel() {
  extern __shared__ uint32_t sm[];
  uint32_t* Qs = sm + QS_OFF;     // [n][d]  stride 68
  uint32_t* Ks = sm + KS_OFF;     // [m][d]  stride 68
  uint32_t* Vt = sm + VT_OFF;     // [d][m]  stride 264
  float*    Ps = (float*)(sm + PS_OFF);  // [n][m] stride 260
  uint32_t* PsU = sm + PS_OFF;

  int t = threadIdx.x;
  int b = blockIdx.y >> 3, h = blockIdx.y & 7;
  int n0 = blockIdx.x * 64;
  int w = t >> 5, l = t & 31;
  int g = l >> 2, tg = l & 3;

  const float* qkvb = g_qkv + (size_t)b * NSEQ * QKV3 + h * DH;

  // ---- stage K [m][d], V transposed [d][m], Q [n][d] (tf32) ----
  {
    int c16 = t & 15, r16 = t >> 4;   // r16 0..31
    int d0 = c16 * 4;
    #pragma unroll
    for (int i = 0; i < 8; ++i) {
      int m = r16 + i * 32;
      const float* rowp = qkvb + (size_t)m * QKV3;
      float4 k4 = *(const float4*)(rowp + DIMC + d0);
      uint4 ku = {f2tf(k4.x), f2tf(k4.y), f2tf(k4.z), f2tf(k4.w)};
      *(uint4*)&Ks[m * 68 + d0] = ku;
      float4 v4 = *(const float4*)(rowp + 2 * DIMC + d0);
      Vt[(d0 + 0) * 264 + m] = f2tf(v4.x);
      Vt[(d0 + 1) * 264 + m] = f2tf(v4.y);
      Vt[(d0 + 2) * 264 + m] = f2tf(v4.z);
      Vt[(d0 + 3) * 264 + m] = f2tf(v4.w);
    }
    #pragma unroll
    for (int i = 0; i < 2; ++i) {
      int n = r16 + i * 32;
      const float* rowp = qkvb + (size_t)(n0 + n) * QKV3;
      float4 q4 = *(const float4*)(rowp + d0);
      uint4 qu = {f2tf(q4.x), f2tf(q4.y), f2tf(q4.z), f2tf(q4.w)};
      *(uint4*)&Qs[n * 68 + d0] = qu;
    }
  }
  __syncthreads();

  // ---- scores S[64][256] = Q @ K^T ; warp tile 16x64 (16 warps) ----
  {
    int wm = (w >> 2) * 16;
    int wnn = (w & 3) * 64;
    float s[8][4];
    #pragma unroll
    for (int j = 0; j < 8; ++j)
      #pragma unroll
      for (int q = 0; q < 4; ++q) s[j][q] = 0.f;

    #pragma unroll
    for (int kk = 0; kk < 64; kk += 8) {
      uint32_t a0 = Qs[(wm + g) * 68 + kk + tg];
      uint32_t a1 = Qs[(wm + g + 8) * 68 + kk + tg];
      uint32_t a2 = Qs[(wm + g) * 68 + kk + tg + 4];
      uint32_t a3 = Qs[(wm + g + 8) * 68 + kk + tg + 4];
      uint32_t bf[8][2];
      #pragma unroll
      for (int j = 0; j < 8; ++j) {
        int m0 = wnn + j * 8;
        bf[j][0] = Ks[(m0 + g) * 68 + kk + tg];
        bf[j][1] = Ks[(m0 + g) * 68 + kk + tg + 4];
      }
      #pragma unroll
      for (int j = 0; j < 8; ++j)
        mma_tf32(s[j], a0, a1, a2, a3, bf[j][0], bf[j][1]);
    }
    int r0 = wm + g;
    #pragma unroll
    for (int j = 0; j < 8; ++j) {
      int cc = wnn + j * 8 + tg * 2;
      Ps[r0 * 260 + cc]           = s[j][0] * SCALE;
      Ps[r0 * 260 + cc + 1]       = s[j][1] * SCALE;
      Ps[(r0 + 8) * 260 + cc]     = s[j][2] * SCALE;
      Ps[(r0 + 8) * 260 + cc + 1] = s[j][3] * SCALE;
    }
  }
  __syncthreads();

  // ---- softmax: 4 rows per warp ----
  {
    #pragma unroll
    for (int r = 0; r < 4; ++r) {
      int n = w * 4 + r;
      float* row = &Ps[n * 260];
      float vals[8];
      float vmax = -1e30f;
      #pragma unroll
      for (int i = 0; i < 8; ++i) {
        vals[i] = row[l + i * 32];
        vmax = fmaxf(vmax, vals[i]);
      }
      #pragma unroll
      for (int o = 16; o; o >>= 1)
        vmax = fmaxf(vmax, __shfl_xor_sync(0xffffffffu, vmax, o));
      float ssum = 0.f;
      #pragma unroll
      for (int i = 0; i < 8; ++i) { vals[i] = __expf(vals[i] - vmax); ssum += vals[i]; }
      #pragma unroll
      for (int o = 16; o; o >>= 1) ssum += __shfl_xor_sync(0xffffffffu, ssum, o);
      float inv = 1.f / ssum;
      float* gA = &g_attn[((size_t)(b * 8 + h) * 256 + n0 + n) * 256];
      #pragma unroll
      for (int i = 0; i < 8; ++i) {
        float a = vals[i] * inv;
        gA[l + i * 32] = a;
        PsU[n * 260 + l + i * 32] = f2tf(a);
      }
    }
  }
  __syncthreads();

  // ---- O[64][64] = P @ V ; warp tile 16x16 ----
  {
    int wm = (w >> 2) * 16;
    int wd = (w & 3) * 16;
    float oc[2][4];
    #pragma unroll
    for (int j = 0; j < 2; ++j)
      #pragma unroll
      for (int q = 0; q < 4; ++q) oc[j][q] = 0.f;

    #pragma unroll 8
    for (int kk = 0; kk < 256; kk += 8) {
      uint32_t a0 = PsU[(wm + g) * 260 + kk + tg];
      uint32_t a1 = PsU[(wm + g + 8) * 260 + kk + tg];
      uint32_t a2 = PsU[(wm + g) * 260 + kk + tg + 4];
      uint32_t a3 = PsU[(wm + g + 8) * 260 + kk + tg + 4];
      uint32_t bf[2][2];
      #pragma unroll
      for (int j = 0; j < 2; ++j) {
        int d0 = wd + j * 8;
        bf[j][0] = Vt[(d0 + g) * 264 + kk + tg];
        bf[j][1] = Vt[(d0 + g) * 264 + kk + tg + 4];
      }
      #pragma unroll
      for (int j = 0; j < 2; ++j)
        mma_tf32(oc[j], a0, a1, a2, a3, bf[j][0], bf[j][1]);
    }
    int n = n0 + wm + g;
    #pragma unroll
    for (int j = 0; j < 2; ++j) {
      int dd = h * 64 + wd + j * 8 + tg * 2;
      float2 v0 = {oc[j][0], oc[j][1]};
      float2 v1 = {oc[j][2], oc[j][3]};
      *(float2*)&g_o[(size_t)(b * 256 + n) * 512 + dd] = v0;
      *(float2*)&g_o[(size_t)(b * 256 + n + 8) * 512 + dd] = v1;
    }
  }
}

// =================================================================
// rpos v5: out2[b,h,n,d] += Σ_m attn[b,h,n,m] * T[idx[n,m], h*64+d]
// Lane owns 4 d-cols (LDG.128/row); half-warps split m; 4-deep prefetch;
// attn staged transposed [m][b] so per-m read = 2 broadcast LDS.128.
// =================================================================
__global__ __launch_bounds__(256) void rpos_kernel(
    const float* __restrict__ table, const int* __restrict__ idx_map) {
  int n = blockIdx.x, h = blockIdx.y;
  __shared__ float sAT[256][12];     // [m][b], padded stride 12
  __shared__ int   sIdx[256];
  __shared__ float sPart[8][8][64];  // [warp][b][d]

  int t = threadIdx.x;
  sIdx[t] = idx_map[n * 256 + t];
  #pragma unroll
  for (int b = 0; b < 8; ++b)
    sAT[t][b] = g_attn[((size_t)(b * 8 + h) * 256 + n) * 256 + t];
  __syncthreads();

  int w = t >> 5, l = t & 31;
  int hw = l >> 4, dl = l & 15;     // d = dl*4
  int base = w * 32 + hw;           // this thread's m = base + 2*i

  float acc[8][4];
  #pragma unroll
  for (int b = 0; b < 8; ++b)
    #pragma unroll
    for (int q = 0; q < 4; ++q) acc[b][q] = 0.f;

  const float* tb = table + h * DH + dl * 4;

  float4 buf[4];
  #pragma unroll
  for (int i = 0; i < 4; ++i)
    buf[i] = *(const float4*)&tb[(size_t)sIdx[base + 2 * i] * DIMC];

  #pragma unroll
  for (int i = 0; i < 16; ++i) {
    float4 tv = buf[i & 3];
    if (i + 4 < 16)
      buf[i & 3] = *(const float4*)&tb[(size_t)sIdx[base + 2 * (i + 4)] * DIMC];
    int m = base + 2 * i;
    float4 aa0 = *(const float4*)&sAT[m][0];
    float4 aa1 = *(const float4*)&sAT[m][4];
    acc[0][0] += aa0.x * tv.x; acc[0][1] += aa0.x * tv.y;
    acc[0][2] += aa0.x * tv.z; acc[0][3] += aa0.x * tv.w;
    acc[1][0] += aa0.y * tv.x; acc[1][1] += aa0.y * tv.y;
    acc[1][2] += aa0.y * tv.z; acc[1][3] += aa0.y * tv.w;
    acc[2][0] += aa0.z * tv.x; acc[2][1] += aa0.z * tv.y;
    acc[2][2] += aa0.z * tv.z; acc[2][3] += aa0.z * tv.w;
    acc[3][0] += aa0.w * tv.x; acc[3][1] += aa0.w * tv.y;
    acc[3][2] += aa0.w * tv.z; acc[3][3] += aa0.w * tv.w;
    acc[4][0] += aa1.x * tv.x; acc[4][1] += aa1.x * tv.y;
    acc[4][2] += aa1.x * tv.z; acc[4][3] += aa1.x * tv.w;
    acc[5][0] += aa1.y * tv.x; acc[5][1] += aa1.y * tv.y;
    acc[5][2] += aa1.y * tv.z; acc[5][3] += aa1.y * tv.w;
    acc[6][0] += aa1.z * tv.x; acc[6][1] += aa1.z * tv.y;
    acc[6][2] += aa1.z * tv.z; acc[6][3] += aa1.z * tv.w;
    acc[7][0] += aa1.w * tv.x; acc[7][1] += aa1.w * tv.y;
    acc[7][2] += aa1.w * tv.z; acc[7][3] += aa1.w * tv.w;
  }

  // combine the two half-warps (same d, complementary m)
  #pragma unroll
  for (int b = 0; b < 8; ++b)
    #pragma unroll
    for (int q = 0; q < 4; ++q)
      acc[b][q] += __shfl_xor_sync(0xffffffffu, acc[b][q], 16);

  if (hw == 0) {
    #pragma unroll
    for (int b = 0; b < 8; ++b) {
      float4 v = {acc[b][0], acc[b][1], acc[b][2], acc[b][3]};
      *(float4*)&sPart[w][b][dl * 4] = v;
    }
  }
  __syncthreads();

  #pragma unroll
  for (int o = t; o < 512; o += 256) {
    int b = o >> 6, d = o & 63;
    float s2 = 0.f;
    #pragma unroll
    for (int w2 = 0; w2 < 8; ++w2) s2 += sPart[w2][b][d];
    g_o[(size_t)(b * 256 + n) * 512 + h * 64 + d] += s2;
  }
}

// =================================================================
extern "C" void kernel_launch(void* const* d_in, const int* in_sizes, int n_in,
                              void* d_out, int out_size) {
  const float* x      = (const float*)d_in[0];
  const float* ln_g   = (const float*)d_in[1];
  const float* ln_b   = (const float*)d_in[2];
  const float* w_qkv  = (const float*)d_in[3];
  const float* table  = (const float*)d_in[4];
  const float* w_out  = (const float*)d_in[5];
  const float* b_out  = (const float*)d_in[6];
  const int*   idxmap = (const int*)d_in[7];
  float* out = (float*)d_out;

  cudaFuncSetAttribute(attn_kernel, cudaFuncAttributeMaxDynamicSharedMemorySize,
                       ATTN_SMEM_BYTES);

  void *p_xn, *p_qkv, *p_o;
  cudaGetSymbolAddress(&p_xn, g_xn);
  cudaGetSymbolAddress(&p_qkv, g_qkv);
  cudaGetSymbolAddress(&p_o, g_o);

  // 1. LayerNorm
  ln_kernel<<<NTOK, 256>>>(x, ln_g, ln_b);

  // 2. qkv = xn @ w_qkv   (2048 x 1536 x 512), BN=128
  gemm_tf32<128, 2, 4><<<dim3(QKV3 / 128, NTOK / 128), 256>>>(
      (const float*)p_xn, w_qkv, nullptr, (float*)p_qkv, NTOK, QKV3, DIMC);

  // 3. attention (scores, softmax, attn·V), 512 threads
  attn_kernel<<<dim3(4, NB * NHEADS), 512, ATTN_SMEM_BYTES>>>();

  // 4. relative-position contribution
  rpos_kernel<<<dim3(NSEQ, NHEADS), 256>>>(table, idxmap);

  // 5. out = g_o @ w_out + b_out   (2048 x 512 x 512), BN=64
  gemm_tf32<64, 4, 2><<<dim3(DIMC / 64, NTOK / 128), 256>>>(
      (const float*)p_o, w_out, b_out, out, NTOK, DIMC, DIMC);
}